// round 9
// baseline (speedup 1.0000x reference)
#include <cuda_runtime.h>
#include <cuda_fp16.h>
#include <cstdint>
#include <math.h>

#define SQ 512
#define HD 512
#define NB 256

// ---------------- device scratch ----------------
__device__ float g_a[1024 * 512];     // a = f@W1[:H] + b1 (folded)
__device__ float g_c[1024 * 512];     // c = f@W1[H:]
__device__ __half g_w2t[NB * HD];     // W2^T fp16 [n][k]

// ---------------- pair-kernel smem layout (bytes) ----------------
static constexpr int SM_A   = 0;        // [buf2][128 rows][128B]  2*16384
static constexpr int SM_B   = 32768;    // [buf2][256 rows][128B]  2*32768
static constexpr int SM_ACS = 98304;    // [buf3][24 rows][272B]   3*6528
static constexpr int SM_B2  = 117888;   // 1024
static constexpr int SM_W3  = 118912;   // 1024
static constexpr int SM_PSM = 119936;   // 128*4 floats = 2048
static constexpr int SMEM_TOTAL = 121984;

__device__ __forceinline__ uint32_t smem_u32(const void* p) {
    uint32_t a;
    asm("{ .reg .u64 t; cvta.to.shared.u64 t, %1; cvt.u32.u64 %0, t; }" : "=r"(a) : "l"(p));
    return a;
}
__device__ __forceinline__ uint32_t sw128(uint32_t off) { return off ^ ((off >> 3) & 0x70); }
__device__ __forceinline__ uint32_t cvt_f16x2(float lo, float hi) {
    __half2 h = __floats2half2_rn(lo, hi);
    return *(uint32_t*)&h;
}

#define LDSM4(r, a) \
    asm volatile("ldmatrix.sync.aligned.m8n8.x4.shared.b16 {%0,%1,%2,%3}, [%4];" \
        : "=r"((r)[0]), "=r"((r)[1]), "=r"((r)[2]), "=r"((r)[3]) : "r"(a))

#define MMA16816(c, a, b0v, b1v) \
    asm volatile("mma.sync.aligned.m16n8k16.row.col.f32.f16.f16.f32 " \
        "{%0,%1,%2,%3}, {%4,%5,%6,%7}, {%8,%9}, {%0,%1,%2,%3};" \
        : "+f"((c)[0]), "+f"((c)[1]), "+f"((c)[2]), "+f"((c)[3]) \
        : "r"((a)[0]), "r"((a)[1]), "r"((a)[2]), "r"((a)[3]), "r"(b0v), "r"(b1v))

#define CP16(dst, src) \
    asm volatile("cp.async.cg.shared.global [%0], [%1], 16;" :: "r"(dst), "l"(src) : "memory")
#define CP_COMMIT()  asm volatile("cp.async.commit_group;" ::: "memory")
#define CP_WAIT0()   asm volatile("cp.async.wait_group 0;" ::: "memory")
#define CP_WAIT1()   asm volatile("cp.async.wait_group 1;" ::: "memory")
#define CP_WAIT2()   asm volatile("cp.async.wait_group 2;" ::: "memory")

#define BAR_SYNC(id, cnt)   asm volatile("bar.sync %0, %1;"   :: "r"(id), "r"(cnt) : "memory")
#define BAR_ARRIVE(id, cnt) asm volatile("bar.arrive %0, %1;" :: "r"(id), "r"(cnt) : "memory")
// barrier ids: 1=READY0 2=READY1 3=FREE0 4=FREE1 5=PROD

// =====================================================================
// Kernel A: a/c projections, 64x64 tiles, cp.async 3-stage, b1 folded
// =====================================================================
__global__ __launch_bounds__(256) void gemm_ac_kernel(const float* __restrict__ f,
                                                      const float* __restrict__ W1,
                                                      const float* __restrict__ b1) {
    const int z = blockIdx.z;
    const float* W = W1 + (size_t)z * HD * HD;
    float* out = z ? g_c : g_a;
    const int m0 = blockIdx.y * 64;
    const int n0 = blockIdx.x * 64;

    __shared__ float fs[3][64][36];   // [stage][m][k32] (pitch 36 -> 16B aligned)
    __shared__ float ws[3][32][64];   // [stage][k][n]

    const int tid = threadIdx.x;
    const int tx = tid & 15, ty = tid >> 4;

    auto pf = [&](int c) {
        int st = c % 3, k0 = c * 32;
#pragma unroll
        for (int u = 0; u < 2; ++u) {   // fs: 64 rows x 8 float4
            int s = u * 256 + tid;
            int m = s >> 3, g = s & 7;
            CP16(smem_u32(&fs[st][m][g * 4]), f + (size_t)(m0 + m) * HD + k0 + g * 4);
        }
#pragma unroll
        for (int u = 0; u < 2; ++u) {   // ws: 32 rows x 16 float4
            int s = u * 256 + tid;
            int kk = s >> 4, g = s & 15;
            CP16(smem_u32(&ws[st][kk][g * 4]), W + (size_t)(k0 + kk) * HD + n0 + g * 4);
        }
        CP_COMMIT();
    };

    pf(0); pf(1);

    float acc[4][4];
#pragma unroll
    for (int r = 0; r < 4; r++)
#pragma unroll
        for (int c = 0; c < 4; c++) acc[r][c] = 0.f;

    for (int c = 0; c < 16; ++c) {
        CP_WAIT1();          // chunk c landed (chunk c+1 may be pending)
        __syncthreads();
        const int st = c % 3;
#pragma unroll
        for (int hh = 0; hh < 32; ++hh) {
            float fv[4];
#pragma unroll
            for (int r = 0; r < 4; r++) fv[r] = fs[st][ty * 4 + r][hh];
            float4 wv = *(const float4*)&ws[st][hh][tx * 4];
#pragma unroll
            for (int r = 0; r < 4; r++) {
                acc[r][0] += fv[r] * wv.x;
                acc[r][1] += fv[r] * wv.y;
                acc[r][2] += fv[r] * wv.z;
                acc[r][3] += fv[r] * wv.w;
            }
        }
        if (c + 2 < 16) pf(c + 2);
        else CP_COMMIT();    // keep group count aligned
    }

    float4 bv = make_float4(0.f, 0.f, 0.f, 0.f);
    if (z == 0) bv = *(const float4*)&b1[n0 + tx * 4];
#pragma unroll
    for (int r = 0; r < 4; r++) {
        float4 o = make_float4(acc[r][0] + bv.x, acc[r][1] + bv.y,
                               acc[r][2] + bv.z, acc[r][3] + bv.w);
        *(float4*)&out[(size_t)(m0 + ty * 4 + r) * HD + n0 + tx * 4] = o;
    }
}

// =====================================================================
// Kernel B: W2 -> fp16 transposed [n][k]
// =====================================================================
__global__ void w2prep_kernel(const float* __restrict__ W2) {
    int idx = blockIdx.x * 256 + threadIdx.x;
    int k = idx >> 8, n = idx & 255;
    g_w2t[n * HD + k] = __float2half_rn(W2[idx]);
}

// =====================================================================
// Kernel C: warp-specialized pair MLP (round-7 proven sync skeleton).
// 384 threads: tid 0..255 = 8 consumer warps grid 2(M)x4(N), consumers
// copy their own B via cp.async; tid 256..383 = 4 producer warps
// (acs cp.async + h1 build + A STS). READY[t&1]/FREE[t&1] parity bars.
// =====================================================================
__global__ __launch_bounds__(384, 1) void pair_hmma_ws_kernel(
    const float* __restrict__ b2, const float* __restrict__ W3,
    const float* __restrict__ b3, float* __restrict__ out) {

    extern __shared__ char smem[];
    const int tid = threadIdx.x;
    const int bz = blockIdx.z;
    const int i0 = blockIdx.y * 8;
    const int j0 = blockIdx.x * 16;
    const uint32_t smb = smem_u32(smem);

    float* b2s = (float*)(smem + SM_B2);
    float* w3s = (float*)(smem + SM_W3);
    float* psm = (float*)(smem + SM_PSM);

    if (tid < 256) {
        // ================= CONSUMERS =================
        const int wid = tid >> 5, lid = tid & 31;
        const int wm = wid >> 2;          // 0..1 : 64-row half of M
        const int wn = wid & 3;           // 0..3 : 64-col quarter of N

        if (tid < 64) ((float4*)b2s)[tid] = ((const float4*)b2)[tid];
        else if (tid < 128) ((float4*)w3s)[tid - 64] = ((const float4*)W3)[tid - 64];

        // B(0) prefetch (8 x 16B per thread)
        {
            char* base = (char*)smem + SM_B;
#pragma unroll
            for (int u = 0; u < 8; ++u) {
                int s = u * 256 + tid;
                int n = s >> 3, g = s & 7;
                uint32_t dst = smem_u32(base) + sw128((uint32_t)(n * 128 + g * 16));
                CP16(dst, g_w2t + (size_t)n * HD + g * 8);
            }
            CP_COMMIT();
        }

        float acc[4][8][4];
#pragma unroll
        for (int mf = 0; mf < 4; mf++)
#pragma unroll
            for (int nf = 0; nf < 8; nf++)
#pragma unroll
                for (int e = 0; e < 4; e++) acc[mf][nf][e] = 0.f;

        const uint32_t xorK = (uint32_t)((lid & 7) << 4);
        const uint32_t khb  = (uint32_t)((lid >> 4) << 4);
        const uint32_t rAb  = (uint32_t)(wm * 64 + (lid & 15));
        const uint32_t rBb  = (uint32_t)(wn * 64 + (lid & 15));

        for (int t = 0; t < 8; ++t) {
            CP_WAIT0();                       // B(t) landed (this thread's copies)
            BAR_SYNC(1 + (t & 1), 384);       // READY: A(t) built; all consumers at bar -> B(t) visible

            if (t + 1 < 8) {                  // B(t+1) copy overlaps MMA(t)
                char* base = (char*)smem + SM_B + ((t + 1) & 1) * 32768;
#pragma unroll
                for (int u = 0; u < 8; ++u) {
                    int s = u * 256 + tid;
                    int n = s >> 3, g = s & 7;
                    uint32_t dst = smem_u32(base) + sw128((uint32_t)(n * 128 + g * 16));
                    CP16(dst, g_w2t + (size_t)n * HD + (t + 1) * 64 + g * 8);
                }
                CP_COMMIT();
            }

            const uint32_t Ah = smb + SM_A + (t & 1) * 16384;
            const uint32_t Bh = smb + SM_B + (t & 1) * 32768;
#pragma unroll
            for (int ks = 0; ks < 4; ++ks) {
                const uint32_t ko = ((uint32_t)(ks * 32) + khb) ^ xorK;
                uint32_t af[4][4];
#pragma unroll
                for (int mf = 0; mf < 4; ++mf)
                    LDSM4(af[mf], Ah + (rAb + mf * 16) * 128 + ko);
#pragma unroll
                for (int nfp = 0; nfp < 4; ++nfp) {
                    uint32_t bf[4];
                    LDSM4(bf, Bh + (rBb + nfp * 16) * 128 + ko);
#pragma unroll
                    for (int mf = 0; mf < 4; ++mf) {
                        MMA16816(acc[mf][2 * nfp],     af[mf], bf[0], bf[2]);
                        MMA16816(acc[mf][2 * nfp + 1], af[mf], bf[1], bf[3]);
                    }
                }
            }
            if (t < 6) BAR_ARRIVE(3 + (t & 1), 384);   // FREE[t&1]
        }

        // epilogue: relu(+b2) . W3, reduce over lane quads, psm
        float pr[4][2];
#pragma unroll
        for (int mf = 0; mf < 4; ++mf) { pr[mf][0] = 0.f; pr[mf][1] = 0.f; }
#pragma unroll
        for (int nf = 0; nf < 8; ++nf) {
            const int n = wn * 64 + nf * 8 + 2 * (lid & 3);
            const float b2x = b2s[n], b2y = b2s[n + 1];
            const float w3x = w3s[n], w3y = w3s[n + 1];
#pragma unroll
            for (int mf = 0; mf < 4; ++mf) {
                pr[mf][0] += fmaxf(acc[mf][nf][0] + b2x, 0.f) * w3x
                           + fmaxf(acc[mf][nf][1] + b2y, 0.f) * w3y;
                pr[mf][1] += fmaxf(acc[mf][nf][2] + b2x, 0.f) * w3x
                           + fmaxf(acc[mf][nf][3] + b2y, 0.f) * w3y;
            }
        }
#pragma unroll
        for (int mf = 0; mf < 4; ++mf)
#pragma unroll
            for (int h = 0; h < 2; ++h) {
                pr[mf][h] += __shfl_xor_sync(0xffffffffu, pr[mf][h], 1);
                pr[mf][h] += __shfl_xor_sync(0xffffffffu, pr[mf][h], 2);
            }
        if ((lid & 3) == 0) {
#pragma unroll
            for (int mf = 0; mf < 4; ++mf)
#pragma unroll
                for (int h = 0; h < 2; ++h) {
                    int row = wm * 64 + mf * 16 + (lid >> 2) + h * 8;
                    psm[row * 4 + wn] = pr[mf][h];
                }
        }
    } else {
        // ================= PRODUCERS (round-7 verbatim) =================
        const int p = tid - 256;              // 0..127
        const int iloc = p >> 4, jloc = p & 15;
        const uint32_t aXor = (uint32_t)((p & 7) << 4);

        auto prefetch_acs = [&](int u) {
            char* acb = (char*)smem + SM_ACS + (u % 3) * 6528;
#pragma unroll
            for (int u2 = 0; u2 < 3; ++u2) {
                int s = u2 * 128 + p;         // 0..383 over 24 rows x 16
                int row = s >> 4, g = s & 15;
                const float* src = (row < 8)
                    ? g_a + ((size_t)(bz * SQ + i0 + row)) * HD + u * 64 + g * 4
                    : g_c + ((size_t)(bz * SQ + j0 + (row - 8))) * HD + u * 64 + g * 4;
                uint32_t dst = smem_u32(acb) + (uint32_t)(row * 272 + g * 16);
                CP16(dst, src);
            }
            CP_COMMIT();
        };

        prefetch_acs(0);
        prefetch_acs(1);

        for (int u = 0; u < 8; ++u) {
            if (u + 2 < 8) prefetch_acs(u + 2);
            if (u < 6) { CP_WAIT2(); } else if (u == 6) { CP_WAIT1(); } else { CP_WAIT0(); }
            BAR_SYNC(5, 128);                 // acs(u) visible to all producers
            if (u >= 2) BAR_SYNC(3 + (u & 1), 384);   // FREE[u&1]: consumers off A[u&1]

            // build A(u): h1 = relu((a_i+b1) + c_j) -> fp16, 64 k values
            const char* acb = (const char*)smem + SM_ACS + (u % 3) * 6528;
            const float* arow = (const float*)(acb + iloc * 272);
            const float* crow = (const float*)(acb + (8 + jloc) * 272);
            uint32_t hv[32];
#pragma unroll
            for (int q = 0; q < 16; ++q) {
                float4 av = *(const float4*)(arow + q * 4);
                float4 cv = *(const float4*)(crow + q * 4);
                float v0 = fmaxf(av.x + cv.x, 0.f);
                float v1 = fmaxf(av.y + cv.y, 0.f);
                float v2 = fmaxf(av.z + cv.z, 0.f);
                float v3 = fmaxf(av.w + cv.w, 0.f);
                hv[q * 2]     = cvt_f16x2(v0, v1);
                hv[q * 2 + 1] = cvt_f16x2(v2, v3);
            }
            char* ah = (char*)smem + SM_A + (u & 1) * 16384;
#pragma unroll
            for (int s = 0; s < 8; ++s) {
                uint32_t off = (uint32_t)(p * 128) + (((uint32_t)(s * 16)) ^ aXor);
                *(uint4*)(ah + off) = make_uint4(hv[s*4], hv[s*4+1], hv[s*4+2], hv[s*4+3]);
            }
            BAR_ARRIVE(1 + (u & 1), 384);     // READY[u&1]
        }
    }

    __syncthreads();
    if (tid < 128) {
        const float b3v = __ldg(b3);
        float lg = psm[tid * 4] + psm[tid * 4 + 1] + psm[tid * 4 + 2] + psm[tid * 4 + 3] + b3v;
        const int i = i0 + (tid >> 4);
        const int j = j0 + (tid & 15);
        out[((size_t)bz * SQ + i) * SQ + j] = 1.f / (1.f + __expf(-lg));
    }
}

// =====================================================================
extern "C" void kernel_launch(void* const* d_in, const int* in_sizes, int n_in,
                              void* d_out, int out_size) {
    const float* f  = (const float*)d_in[0];
    const float* W1 = (const float*)d_in[1];
    const float* b1 = (const float*)d_in[2];
    const float* W2 = (const float*)d_in[3];
    const float* b2 = (const float*)d_in[4];
    const float* W3 = (const float*)d_in[5];
    const float* b3 = (const float*)d_in[6];
    float* out = (float*)d_out;

    cudaFuncSetAttribute(pair_hmma_ws_kernel,
                         cudaFuncAttributeMaxDynamicSharedMemorySize, SMEM_TOTAL);

    gemm_ac_kernel<<<dim3(8, 16, 2), 256>>>(f, W1, b1);
    w2prep_kernel<<<512, 256>>>(W2);
    pair_hmma_ws_kernel<<<dim3(32, 64, 2), 384, SMEM_TOTAL>>>(b2, W3, b3, out);
}

// round 10
// speedup vs baseline: 1.0918x; 1.0918x over previous
#include <cuda_runtime.h>
#include <cuda_fp16.h>
#include <cstdint>
#include <math.h>

#define SQ 512
#define HD 512
#define NB 256

// ---------------- device scratch ----------------
__device__ float g_a[1024 * 512];     // a = f@W1[:H] + b1 (folded)
__device__ float g_c[1024 * 512];     // c = f@W1[H:]
__device__ __half g_w2t[NB * HD];     // W2^T fp16 [n][k]

// ---------------- pair-kernel smem layout (bytes) ----------------
static constexpr int SM_A   = 0;        // [buf2][128 rows][128B]  2*16384
static constexpr int SM_B   = 32768;    // [buf2][256 rows][128B]  2*32768
static constexpr int SM_ACS = 98304;    // [buf3][24 rows][272B]   3*6528
static constexpr int SM_B2  = 117888;   // 1024
static constexpr int SM_W3  = 118912;   // 1024
static constexpr int SM_PSM = 119936;   // 1024
static constexpr int SMEM_TOTAL = 120960;

__device__ __forceinline__ uint32_t smem_u32(const void* p) {
    uint32_t a;
    asm("{ .reg .u64 t; cvta.to.shared.u64 t, %1; cvt.u32.u64 %0, t; }" : "=r"(a) : "l"(p));
    return a;
}
__device__ __forceinline__ uint32_t sw128(uint32_t off) { return off ^ ((off >> 3) & 0x70); }
__device__ __forceinline__ uint32_t cvt_f16x2(float lo, float hi) {
    __half2 h = __floats2half2_rn(lo, hi);
    return *(uint32_t*)&h;
}

#define LDSM4(r, a) \
    asm volatile("ldmatrix.sync.aligned.m8n8.x4.shared.b16 {%0,%1,%2,%3}, [%4];" \
        : "=r"((r)[0]), "=r"((r)[1]), "=r"((r)[2]), "=r"((r)[3]) : "r"(a))

#define MMA16816(c, a, b0v, b1v) \
    asm volatile("mma.sync.aligned.m16n8k16.row.col.f32.f16.f16.f32 " \
        "{%0,%1,%2,%3}, {%4,%5,%6,%7}, {%8,%9}, {%0,%1,%2,%3};" \
        : "+f"((c)[0]), "+f"((c)[1]), "+f"((c)[2]), "+f"((c)[3]) \
        : "r"((a)[0]), "r"((a)[1]), "r"((a)[2]), "r"((a)[3]), "r"(b0v), "r"(b1v))

#define CP16(dst, src) \
    asm volatile("cp.async.cg.shared.global [%0], [%1], 16;" :: "r"(dst), "l"(src) : "memory")
#define CP_COMMIT()  asm volatile("cp.async.commit_group;" ::: "memory")
#define CP_WAIT0()   asm volatile("cp.async.wait_group 0;" ::: "memory")
#define CP_WAIT1()   asm volatile("cp.async.wait_group 1;" ::: "memory")
#define CP_WAIT2()   asm volatile("cp.async.wait_group 2;" ::: "memory")

#define BAR_SYNC(id, cnt)   asm volatile("bar.sync %0, %1;"   :: "r"(id), "r"(cnt) : "memory")
#define BAR_ARRIVE(id, cnt) asm volatile("bar.arrive %0, %1;" :: "r"(id), "r"(cnt) : "memory")
// barrier ids: 1=READY0 2=READY1 3=FREE0 4=FREE1 5=PROD

// =====================================================================
// Kernel A: z<2 -> a/c projections (64x64 tiles, cp.async 3-stage, b1
// folded into a); z==2 -> W2 -> fp16 transposed [n][k] (fused prep).
// =====================================================================
__global__ __launch_bounds__(256) void gemm_ac_kernel(const float* __restrict__ f,
                                                      const float* __restrict__ W1,
                                                      const float* __restrict__ b1,
                                                      const float* __restrict__ W2) {
    const int z = blockIdx.z;
    if (z == 2) {
        // w2prep: 131072 elements over 128 blocks x 256 threads x 4 each
        int base = (blockIdx.y * 8 + blockIdx.x) * 1024 + threadIdx.x * 4;
#pragma unroll
        for (int v = 0; v < 4; ++v) {
            int idx = base + v;
            int k = idx >> 8, n = idx & 255;
            g_w2t[n * HD + k] = __float2half_rn(W2[idx]);
        }
        return;
    }

    const float* W = W1 + (size_t)z * HD * HD;
    float* out = z ? g_c : g_a;
    const int m0 = blockIdx.y * 64;
    const int n0 = blockIdx.x * 64;

    __shared__ float fs[3][64][36];   // [stage][m][k32] (pitch 36 -> 16B aligned)
    __shared__ float ws[3][32][64];   // [stage][k][n]

    const int tid = threadIdx.x;
    const int tx = tid & 15, ty = tid >> 4;

    auto pf = [&](int c) {
        int st = c % 3, k0 = c * 32;
#pragma unroll
        for (int u = 0; u < 2; ++u) {   // fs: 64 rows x 8 float4
            int s = u * 256 + tid;
            int m = s >> 3, g = s & 7;
            CP16(smem_u32(&fs[st][m][g * 4]), f + (size_t)(m0 + m) * HD + k0 + g * 4);
        }
#pragma unroll
        for (int u = 0; u < 2; ++u) {   // ws: 32 rows x 16 float4
            int s = u * 256 + tid;
            int kk = s >> 4, g = s & 15;
            CP16(smem_u32(&ws[st][kk][g * 4]), W + (size_t)(k0 + kk) * HD + n0 + g * 4);
        }
        CP_COMMIT();
    };

    pf(0); pf(1);

    float acc[4][4];
#pragma unroll
    for (int r = 0; r < 4; r++)
#pragma unroll
        for (int c = 0; c < 4; c++) acc[r][c] = 0.f;

    for (int c = 0; c < 16; ++c) {
        CP_WAIT1();          // chunk c landed
        __syncthreads();
        const int st = c % 3;
#pragma unroll
        for (int hh = 0; hh < 32; ++hh) {
            float fv[4];
#pragma unroll
            for (int r = 0; r < 4; r++) fv[r] = fs[st][ty * 4 + r][hh];
            float4 wv = *(const float4*)&ws[st][hh][tx * 4];
#pragma unroll
            for (int r = 0; r < 4; r++) {
                acc[r][0] += fv[r] * wv.x;
                acc[r][1] += fv[r] * wv.y;
                acc[r][2] += fv[r] * wv.z;
                acc[r][3] += fv[r] * wv.w;
            }
        }
        if (c + 2 < 16) pf(c + 2);
        else CP_COMMIT();    // keep group count aligned
    }

    float4 bv = make_float4(0.f, 0.f, 0.f, 0.f);
    if (z == 0) bv = *(const float4*)&b1[n0 + tx * 4];
#pragma unroll
    for (int r = 0; r < 4; r++) {
        float4 o = make_float4(acc[r][0] + bv.x, acc[r][1] + bv.y,
                               acc[r][2] + bv.z, acc[r][3] + bv.w);
        *(float4*)&out[(size_t)(m0 + ty * 4 + r) * HD + n0 + tx * 4] = o;
    }
}

// =====================================================================
// Kernel C: warp-specialized pair MLP (round-7 proven layout verbatim).
// 384 threads: tid 0..255 = 8 consumer warps grid 4(M)x2(N);
// tid 256..383 = 4 producer warps (acs cp.async + h1 build + A STS).
// =====================================================================
__global__ __launch_bounds__(384, 1) void pair_hmma_ws_kernel(
    const float* __restrict__ b2, const float* __restrict__ W3,
    const float* __restrict__ b3, float* __restrict__ out) {

    extern __shared__ char smem[];
    const int tid = threadIdx.x;
    const int bz = blockIdx.z;
    const int i0 = blockIdx.y * 8;
    const int j0 = blockIdx.x * 16;
    const uint32_t smb = smem_u32(smem);

    float* b2s = (float*)(smem + SM_B2);
    float* w3s = (float*)(smem + SM_W3);
    float* psm = (float*)(smem + SM_PSM);

    if (tid < 256) {
        // ================= CONSUMERS =================
        const int wid = tid >> 5, lid = tid & 31;
        const int wm = wid >> 1, wn = wid & 1;

        if (tid < 64) ((float4*)b2s)[tid] = ((const float4*)b2)[tid];
        else if (tid < 128) ((float4*)w3s)[tid - 64] = ((const float4*)W3)[tid - 64];

        // B(0) prefetch (8 x 16B per thread)
        {
            char* base = (char*)smem + SM_B;
#pragma unroll
            for (int u = 0; u < 8; ++u) {
                int s = u * 256 + tid;
                int n = s >> 3, g = s & 7;
                uint32_t dst = smem_u32(base) + sw128((uint32_t)(n * 128 + g * 16));
                CP16(dst, g_w2t + (size_t)n * HD + g * 8);
            }
            CP_COMMIT();
        }

        float acc[2][16][4];
#pragma unroll
        for (int mf = 0; mf < 2; mf++)
#pragma unroll
            for (int nf = 0; nf < 16; nf++)
#pragma unroll
                for (int e = 0; e < 4; e++) acc[mf][nf][e] = 0.f;

        const int rA = wm * 32 + (lid & 15);
        const uint32_t xorA = (uint32_t)((rA & 7) << 4);
        const int rB = wn * 128 + (lid & 15);
        const uint32_t xorB = (uint32_t)((rB & 7) << 4);
        const uint32_t khb = (uint32_t)((lid >> 4) << 4);

        for (int t = 0; t < 8; ++t) {
            CP_WAIT0();                       // B(t) landed (this thread)
            BAR_SYNC(1 + (t & 1), 384);       // READY: A(t) built; bar -> B(t) visible

            if (t + 1 < 8) {                  // B(t+1) copy overlaps MMA(t)
                char* base = (char*)smem + SM_B + ((t + 1) & 1) * 32768;
#pragma unroll
                for (int u = 0; u < 8; ++u) {
                    int s = u * 256 + tid;
                    int n = s >> 3, g = s & 7;
                    uint32_t dst = smem_u32(base) + sw128((uint32_t)(n * 128 + g * 16));
                    CP16(dst, g_w2t + (size_t)n * HD + (t + 1) * 64 + g * 8);
                }
                CP_COMMIT();
            }

            const uint32_t Ah = smb + SM_A + (t & 1) * 16384;
            const uint32_t Bh = smb + SM_B + (t & 1) * 32768;
#pragma unroll
            for (int ks = 0; ks < 4; ++ks) {
                const uint32_t koff = ((uint32_t)(ks * 32) + khb);
                const uint32_t aoff = (uint32_t)(rA * 128) + (koff ^ xorA);
                uint32_t ah0[4], ah1[4];
                LDSM4(ah0, Ah + aoff);
                LDSM4(ah1, Ah + aoff + 16 * 128);
                const uint32_t bko = koff ^ xorB;
#pragma unroll
                for (int nfp = 0; nfp < 8; ++nfp) {
                    uint32_t boff = (uint32_t)((rB + nfp * 16) * 128) + bko;
                    uint32_t bh[4];
                    LDSM4(bh, Bh + boff);
                    MMA16816(acc[0][2 * nfp],     ah0, bh[0], bh[2]);
                    MMA16816(acc[0][2 * nfp + 1], ah0, bh[1], bh[3]);
                    MMA16816(acc[1][2 * nfp],     ah1, bh[0], bh[2]);
                    MMA16816(acc[1][2 * nfp + 1], ah1, bh[1], bh[3]);
                }
            }
            if (t < 6) BAR_ARRIVE(3 + (t & 1), 384);   // FREE[t&1]
        }

        // epilogue: relu(+b2) . W3, reduce, psm
        float pr[2][2] = {{0.f, 0.f}, {0.f, 0.f}};
#pragma unroll
        for (int nf = 0; nf < 16; ++nf) {
            const int n = wn * 128 + nf * 8 + 2 * (lid & 3);
            const float b2x = b2s[n], b2y = b2s[n + 1];
            const float w3x = w3s[n], w3y = w3s[n + 1];
#pragma unroll
            for (int mf = 0; mf < 2; ++mf) {
                pr[mf][0] += fmaxf(acc[mf][nf][0] + b2x, 0.f) * w3x
                           + fmaxf(acc[mf][nf][1] + b2y, 0.f) * w3y;
                pr[mf][1] += fmaxf(acc[mf][nf][2] + b2x, 0.f) * w3x
                           + fmaxf(acc[mf][nf][3] + b2y, 0.f) * w3y;
            }
        }
#pragma unroll
        for (int mf = 0; mf < 2; ++mf)
#pragma unroll
            for (int h = 0; h < 2; ++h) {
                pr[mf][h] += __shfl_xor_sync(0xffffffffu, pr[mf][h], 1);
                pr[mf][h] += __shfl_xor_sync(0xffffffffu, pr[mf][h], 2);
            }
        if ((lid & 3) == 0) {
#pragma unroll
            for (int mf = 0; mf < 2; ++mf)
#pragma unroll
                for (int h = 0; h < 2; ++h) {
                    int row = wm * 32 + mf * 16 + (lid >> 2) + h * 8;
                    psm[row * 2 + wn] = pr[mf][h];
                }
        }
    } else {
        // ================= PRODUCERS =================
        const int p = tid - 256;              // 0..127
        const int iloc = p >> 4, jloc = p & 15;
        const uint32_t aXor = (uint32_t)((p & 7) << 4);

        auto prefetch_acs = [&](int u) {
            char* acb = (char*)smem + SM_ACS + (u % 3) * 6528;
#pragma unroll
            for (int u2 = 0; u2 < 3; ++u2) {
                int s = u2 * 128 + p;         // 0..383 over 24 rows x 16
                int row = s >> 4, g = s & 15;
                const float* src = (row < 8)
                    ? g_a + ((size_t)(bz * SQ + i0 + row)) * HD + u * 64 + g * 4
                    : g_c + ((size_t)(bz * SQ + j0 + (row - 8))) * HD + u * 64 + g * 4;
                uint32_t dst = smem_u32(acb) + (uint32_t)(row * 272 + g * 16);
                CP16(dst, src);
            }
            CP_COMMIT();
        };

        prefetch_acs(0);
        prefetch_acs(1);

        for (int u = 0; u < 8; ++u) {
            if (u + 2 < 8) prefetch_acs(u + 2);
            if (u < 6) { CP_WAIT2(); } else if (u == 6) { CP_WAIT1(); } else { CP_WAIT0(); }
            BAR_SYNC(5, 128);                 // acs(u) visible to all producers
            if (u >= 2) BAR_SYNC(3 + (u & 1), 384);   // FREE[u&1]: consumers off A[u&1]

            // build A(u): h1 = relu((a_i+b1) + c_j) -> fp16, 64 k values
            const char* acb = (const char*)smem + SM_ACS + (u % 3) * 6528;
            const float* arow = (const float*)(acb + iloc * 272);
            const float* crow = (const float*)(acb + (8 + jloc) * 272);
            uint32_t hv[32];
#pragma unroll
            for (int q = 0; q < 16; ++q) {
                float4 av = *(const float4*)(arow + q * 4);
                float4 cv = *(const float4*)(crow + q * 4);
                float v0 = fmaxf(av.x + cv.x, 0.f);
                float v1 = fmaxf(av.y + cv.y, 0.f);
                float v2 = fmaxf(av.z + cv.z, 0.f);
                float v3 = fmaxf(av.w + cv.w, 0.f);
                hv[q * 2]     = cvt_f16x2(v0, v1);
                hv[q * 2 + 1] = cvt_f16x2(v2, v3);
            }
            char* ah = (char*)smem + SM_A + (u & 1) * 16384;
#pragma unroll
            for (int s = 0; s < 8; ++s) {
                uint32_t off = (uint32_t)(p * 128) + (((uint32_t)(s * 16)) ^ aXor);
                *(uint4*)(ah + off) = make_uint4(hv[s*4], hv[s*4+1], hv[s*4+2], hv[s*4+3]);
            }
            BAR_ARRIVE(1 + (u & 1), 384);     // READY[u&1]
        }
    }

    __syncthreads();
    if (tid < 128) {
        const float b3v = __ldg(b3);
        float lg = psm[tid * 2] + psm[tid * 2 + 1] + b3v;
        const int i = i0 + (tid >> 4);
        const int j = j0 + (tid & 15);
        out[((size_t)bz * SQ + i) * SQ + j] = 1.f / (1.f + __expf(-lg));
    }
}

// =====================================================================
extern "C" void kernel_launch(void* const* d_in, const int* in_sizes, int n_in,
                              void* d_out, int out_size) {
    const float* f  = (const float*)d_in[0];
    const float* W1 = (const float*)d_in[1];
    const float* b1 = (const float*)d_in[2];
    const float* W2 = (const float*)d_in[3];
    const float* b2 = (const float*)d_in[4];
    const float* W3 = (const float*)d_in[5];
    const float* b3 = (const float*)d_in[6];
    float* out = (float*)d_out;

    cudaFuncSetAttribute(pair_hmma_ws_kernel,
                         cudaFuncAttributeMaxDynamicSharedMemorySize, SMEM_TOTAL);

    gemm_ac_kernel<<<dim3(8, 16, 3), 256>>>(f, W1, b1, W2);
    pair_hmma_ws_kernel<<<dim3(32, 64, 2), 384, SMEM_TOTAL>>>(b2, W3, b3, out);
}